// round 1
// baseline (speedup 1.0000x reference)
#include <cuda_runtime.h>
#include <cuda_bf16.h>

// Problem constants (fixed shapes)
#define SEQ    512
#define BATCH  65536
#define HID    2

// MLP tiling
#define BT     64          // batch tile per block
#define OC     64          // output-column chunk staged in smem
#define NT     256         // threads per block
#define SSTR   260         // smem row stride in floats (keeps float4 alignment, spreads banks)

// Scratch for RNN final hidden state [BATCH, 2]
__device__ float g_hidden[BATCH * HID];

// ---------------------------------------------------------------------------
// Fast accurate-enough tanh: 1 - 2/(e^{2x}+1). Handles +-inf saturation.
// __expf ~2^-22 rel, __fdividef ~2^-22 rel -> plenty under 1e-3 tolerance.
// ---------------------------------------------------------------------------
__device__ __forceinline__ float tanh_fast(float x) {
    float e = __expf(2.0f * x);
    return 1.0f - __fdividef(2.0f, e + 1.0f);
}

// ---------------------------------------------------------------------------
// Kernel 1: RNN scan. One thread per batch element. Memory-bound on x (256MB).
// ---------------------------------------------------------------------------
__global__ __launch_bounds__(256) void rnn_kernel(
    const float* __restrict__ x,
    const float* __restrict__ w_ih, const float* __restrict__ b_ih,
    const float* __restrict__ w_hh, const float* __restrict__ b_hh)
{
    int b = blockIdx.x * blockDim.x + threadIdx.x;   // 0..BATCH-1

    // broadcast weights (tiny, L2/L1 resident)
    float a00 = w_ih[0], a01 = w_ih[1], a10 = w_ih[2], a11 = w_ih[3];
    float u00 = w_hh[0], u01 = w_hh[1], u10 = w_hh[2], u11 = w_hh[3];
    float c0 = b_ih[0] + b_hh[0];
    float c1 = b_ih[1] + b_hh[1];

    float h0 = 0.0f, h1 = 0.0f;
    const float2* xp = reinterpret_cast<const float2*>(x) + b;

    #pragma unroll 4
    for (int t = 0; t < SEQ; t++) {
        float2 xv = xp[(size_t)t * BATCH];
        float p0 = fmaf(u01, h1, fmaf(u00, h0, fmaf(a01, xv.y, fmaf(a00, xv.x, c0))));
        float p1 = fmaf(u11, h1, fmaf(u10, h0, fmaf(a11, xv.y, fmaf(a10, xv.x, c1))));
        h0 = tanh_fast(p0);
        h1 = tanh_fast(p1);
    }
    reinterpret_cast<float2*>(g_hidden)[b] = make_float2(h0, h1);
}

// ---------------------------------------------------------------------------
// Kernel 2: fused 5-layer MLP head (fp32 baseline).
//   L1: 2 -> 256 (relu)     trivial, computed directly from g_hidden
//   L2..L4: 256 -> 256 (relu) register-tiled GEMM, weights chunked in smem
//   L5: 256 -> 2             small epilogue
// Block: 256 threads handle a BT=64 batch tile. Activations ping-pong in smem.
// ---------------------------------------------------------------------------
__global__ __launch_bounds__(NT, 1) void mlp_kernel(
    const float* __restrict__ w1, const float* __restrict__ b1,
    const float* __restrict__ w2, const float* __restrict__ b2,
    const float* __restrict__ w3, const float* __restrict__ b3,
    const float* __restrict__ w4, const float* __restrict__ b4,
    const float* __restrict__ w5, const float* __restrict__ b5,
    float* __restrict__ out)
{
    extern __shared__ float smem[];
    float* bufA = smem;                       // BT * SSTR
    float* bufB = smem + BT * SSTR;           // BT * SSTR
    float* sW   = smem + 2 * BT * SSTR;       // OC * SSTR

    const int tid = threadIdx.x;
    const int B0  = blockIdx.x * BT;
    const int txo = tid & 15;                 // 16 output-groups
    const int txb = tid >> 4;                 // 16 batch-groups

    // ---- Layer 1: in-dim 2, each thread owns one output column ----
    {
        int o = tid;
        float wa = w1[2 * o], wb = w1[2 * o + 1], bb = b1[o];
        const float2* hp = reinterpret_cast<const float2*>(g_hidden) + B0;
        for (int b = 0; b < BT; b++) {
            float2 hv = hp[b];                           // warp-broadcast load
            float v = fmaf(hv.x, wa, fmaf(hv.y, wb, bb));
            bufA[b * SSTR + o] = fmaxf(v, 0.0f);
        }
    }
    __syncthreads();

    // ---- Layers 2..4: 256x256, relu ----
    const float* Ws[3] = { w2, w3, w4 };
    const float* Bs[3] = { b2, b3, b4 };

    for (int L = 0; L < 3; L++) {
        const float* W  = Ws[L];
        const float* Bv = Bs[L];

        for (int oc = 0; oc < 256; oc += OC) {
            // cooperative load of W[oc..oc+63][0..255] into sW (float4 coalesced)
            const float4* src = reinterpret_cast<const float4*>(W + oc * 256);
            #pragma unroll
            for (int i = tid; i < OC * 64; i += NT) {    // OC*256/4 float4s
                float4 v = src[i];
                int o  = i >> 6;                          // 64 float4 per row
                int k4 = i & 63;
                *reinterpret_cast<float4*>(&sW[o * SSTR + 4 * k4]) = v;
            }
            __syncthreads();

            // register-tiled 64b x 64o compute; thread tile 4x4, rows strided by 16
            float acc[4][4] = {};
            for (int k = 0; k < 256; k += 4) {
                float4 av[4], wv[4];
                #pragma unroll
                for (int i = 0; i < 4; i++)
                    av[i] = *reinterpret_cast<const float4*>(&bufA[(txb + 16 * i) * SSTR + k]);
                #pragma unroll
                for (int j = 0; j < 4; j++)
                    wv[j] = *reinterpret_cast<const float4*>(&sW[(txo + 16 * j) * SSTR + k]);
                #pragma unroll
                for (int i = 0; i < 4; i++) {
                    #pragma unroll
                    for (int j = 0; j < 4; j++) {
                        acc[i][j] = fmaf(av[i].x, wv[j].x, acc[i][j]);
                        acc[i][j] = fmaf(av[i].y, wv[j].y, acc[i][j]);
                        acc[i][j] = fmaf(av[i].z, wv[j].z, acc[i][j]);
                        acc[i][j] = fmaf(av[i].w, wv[j].w, acc[i][j]);
                    }
                }
            }

            // bias + relu, write to output buffer
            #pragma unroll
            for (int j = 0; j < 4; j++) {
                int ocol = oc + txo + 16 * j;
                float bias = Bv[ocol];
                #pragma unroll
                for (int i = 0; i < 4; i++) {
                    float v = acc[i][j] + bias;
                    bufB[(txb + 16 * i) * SSTR + ocol] = fmaxf(v, 0.0f);
                }
            }
            __syncthreads();   // sW consumed + bufB chunk visible before next chunk
        }
        // swap activation buffers
        float* t = bufA; bufA = bufB; bufB = t;
    }

    // ---- Layer 5: 256 -> 2 ----
    // stage w5 (512 floats) in now-free sW
    for (int i = tid; i < 512; i += NT) sW[i] = w5[i];
    __syncthreads();

    if (tid < BT * 2) {
        int b = tid >> 1;
        int c = tid & 1;
        const float* wr = &sW[c * 256];
        float acc = b5[c];
        for (int k = 0; k < 256; k += 4) {
            float4 a = *reinterpret_cast<const float4*>(&bufA[b * SSTR + k]);
            float4 w = *reinterpret_cast<const float4*>(&wr[k]);
            acc = fmaf(a.x, w.x, acc);
            acc = fmaf(a.y, w.y, acc);
            acc = fmaf(a.z, w.z, acc);
            acc = fmaf(a.w, w.w, acc);
        }
        out[(B0 + b) * 2 + c] = acc;
    }
}

// ---------------------------------------------------------------------------
// Launch
// ---------------------------------------------------------------------------
extern "C" void kernel_launch(void* const* d_in, const int* in_sizes, int n_in,
                              void* d_out, int out_size)
{
    const float* x    = (const float*)d_in[0];
    const float* w_ih = (const float*)d_in[1];
    const float* b_ih = (const float*)d_in[2];
    const float* w_hh = (const float*)d_in[3];
    const float* b_hh = (const float*)d_in[4];
    const float* w1   = (const float*)d_in[5];
    const float* b1   = (const float*)d_in[6];
    const float* w2   = (const float*)d_in[7];
    const float* b2   = (const float*)d_in[8];
    const float* w3   = (const float*)d_in[9];
    const float* b3   = (const float*)d_in[10];
    const float* w4   = (const float*)d_in[11];
    const float* b4   = (const float*)d_in[12];
    const float* w5   = (const float*)d_in[13];
    const float* b5   = (const float*)d_in[14];
    float* out        = (float*)d_out;

    rnn_kernel<<<BATCH / 256, 256>>>(x, w_ih, b_ih, w_hh, b_hh);

    const int smem_bytes = (2 * BT + OC) * SSTR * sizeof(float);   // 199,680 B
    cudaFuncSetAttribute(mlp_kernel, cudaFuncAttributeMaxDynamicSharedMemorySize, smem_bytes);
    mlp_kernel<<<BATCH / BT, NT, smem_bytes>>>(w1, b1, w2, b2, w3, b3, w4, b4, w5, b5, out);
}

// round 4
// speedup vs baseline: 2.8585x; 2.8585x over previous
#include <cuda_runtime.h>
#include <cuda_bf16.h>
#include <cstdint>

#define SEQ    512
#define BATCH  65536

// ---------------- MLP config ----------------
#define MT        128               // batch rows per CTA
#define NTH       512               // threads (16 warps: 4 M-groups x 4 N-groups)
#define A_STRIDE  528               // bytes per A row (512 + 16 pad; 33*16B, 33%8==1 -> conflict-free)
#define A_PLANE   (MT * A_STRIDE)   // 67584 B per plane (hi, lo)
#define W_OFF     (2 * A_PLANE)     // 135168
#define W_ROW     80                // bytes per W row (64 + 16 pad; 5*16B, 5%8 coprime)
#define W_PLANE   (256 * W_ROW)     // 20480 B  (256 n-rows x 32 k bf16, padded)
#define W_BUF     (2 * W_PLANE)     // hi+lo planes per k-chunk buffer
#define OSUM_OFF  (W_OFF + 2 * W_BUF)   // 217088
#define SMEM_TOTAL (OSUM_OFF + 1024)    // 218112

__device__ float g_hidden[BATCH * 2];
// weight images: [3 layers][2 planes][8 k-chunks] x [256 n][32 k] bf16, contiguous 16KB each
__device__ __align__(1024) __nv_bfloat16 g_wimg[48 * 8192];

// ======================= helpers =======================
__device__ __forceinline__ uint32_t smem_u32(const void* p) {
    uint32_t a;
    asm("{ .reg .u64 t; cvta.to.shared.u64 t, %1; cvt.u32.u64 %0, t; }" : "=r"(a) : "l"(p));
    return a;
}

#define LDSM4(r, addr) \
    asm volatile("ldmatrix.sync.aligned.m8n8.x4.shared.b16 {%0,%1,%2,%3}, [%4];" \
                 : "=r"((r)[0]), "=r"((r)[1]), "=r"((r)[2]), "=r"((r)[3]) : "r"(addr))

#define MMA_BF16(d, a, b0, b1) \
    asm volatile("mma.sync.aligned.m16n8k16.row.col.f32.bf16.bf16.f32 " \
                 "{%0,%1,%2,%3},{%4,%5,%6,%7},{%8,%9},{%0,%1,%2,%3};" \
                 : "+f"((d)[0]), "+f"((d)[1]), "+f"((d)[2]), "+f"((d)[3]) \
                 : "r"((a)[0]), "r"((a)[1]), "r"((a)[2]), "r"((a)[3]), "r"(b0), "r"(b1))

__device__ __forceinline__ uint32_t pack_bf16x2(float lo, float hi) {
    __nv_bfloat162 t;
    t.x = __float2bfloat16(lo);
    t.y = __float2bfloat16(hi);
    return *reinterpret_cast<uint32_t*>(&t);
}

// ======================= RNN scan =======================
__device__ __forceinline__ float tanh_hw(float x) {
    float y; asm("tanh.approx.f32 %0, %1;" : "=f"(y) : "f"(x)); return y;
}

__global__ __launch_bounds__(256) void rnn_kernel(
    const float* __restrict__ x,
    const float* __restrict__ w_ih, const float* __restrict__ b_ih,
    const float* __restrict__ w_hh, const float* __restrict__ b_hh)
{
    int b = blockIdx.x * blockDim.x + threadIdx.x;
    float a00 = w_ih[0], a01 = w_ih[1], a10 = w_ih[2], a11 = w_ih[3];
    float u00 = w_hh[0], u01 = w_hh[1], u10 = w_hh[2], u11 = w_hh[3];
    float c0 = b_ih[0] + b_hh[0];
    float c1 = b_ih[1] + b_hh[1];

    float h0 = 0.0f, h1 = 0.0f;
    const float2* xp = reinterpret_cast<const float2*>(x) + b;

    #pragma unroll 8
    for (int t = 0; t < SEQ; t++) {
        float2 xv = xp[(size_t)t * BATCH];
        float p0 = fmaf(u01, h1, fmaf(u00, h0, fmaf(a01, xv.y, fmaf(a00, xv.x, c0))));
        float p1 = fmaf(u11, h1, fmaf(u10, h0, fmaf(a11, xv.y, fmaf(a10, xv.x, c1))));
        h0 = tanh_hw(p0);
        h1 = tanh_hw(p1);
    }
    reinterpret_cast<float2*>(g_hidden)[b] = make_float2(h0, h1);
}

// ======================= weight prep: fp32 -> bf16 hi/lo chunk images =======================
__global__ __launch_bounds__(256) void prep_w_kernel(
    const float* __restrict__ w2, const float* __restrict__ w3, const float* __restrict__ w4)
{
    int idx = blockIdx.x * blockDim.x + threadIdx.x;   // 0 .. 3*65536-1
    int L = idx >> 16;
    int r = idx & 65535;          // n*256 + k
    int n = r >> 8, k = r & 255;
    const float* W = (L == 0) ? w2 : (L == 1) ? w3 : w4;
    float v = W[r];
    __nv_bfloat16 h = __float2bfloat16(v);
    __nv_bfloat16 l = __float2bfloat16(v - __bfloat162float(h));
    int kc = k >> 5, kk = k & 31;
    size_t base = ((size_t)((L * 2) * 8 + kc)) * 8192 + n * 32 + kk;
    g_wimg[base]           = h;   // hi plane image
    g_wimg[base + 8 * 8192] = l;  // lo plane image (p=1 -> +8 images)
}

// ======================= fused HMMA MLP =======================
__device__ __forceinline__ void load_chunk(uint32_t sb, int buf, int L, int kc, int tid) {
    #pragma unroll
    for (int i = 0; i < 4; i++) {
        int g  = tid + i * NTH;        // 0..2047 (2 planes x 1024 granules of 16B)
        int p  = g >> 10;
        int gg = g & 1023;
        int n  = gg >> 2, c = gg & 3;
        uint32_t dst = sb + W_OFF + buf * W_BUF + p * W_PLANE + n * W_ROW + c * 16;
        const void* src = (const char*)g_wimg +
            (((size_t)((L * 2 + p) * 8 + kc)) << 14) + ((size_t)gg << 4);
        asm volatile("cp.async.cg.shared.global [%0], [%1], 16;" :: "r"(dst), "l"(src));
    }
    asm volatile("cp.async.commit_group;" ::: "memory");
}

__global__ __launch_bounds__(NTH, 1) void mlp_mma_kernel(
    const float* __restrict__ w1, const float* __restrict__ b1,
    const float* __restrict__ b2, const float* __restrict__ b3,
    const float* __restrict__ b4,
    const float* __restrict__ w5, const float* __restrict__ b5,
    float* __restrict__ out)
{
    extern __shared__ char smem[];
    const uint32_t sb = smem_u32(smem);
    const int tid  = threadIdx.x;
    const int lane = tid & 31;
    const int wrp  = tid >> 5;
    const int wm   = wrp >> 2;          // M-group 0..3
    const int wn   = wrp & 3;           // N-group 0..3
    const int m0   = 32 * wm;
    const int n0   = 64 * wn;
    const int B0   = blockIdx.x * MT;

    // prefetch first two W k-chunks of layer 0
    load_chunk(sb, 0, 0, 0, tid);
    load_chunk(sb, 1, 0, 1, tid);

    // ---- layer 1 (2 -> 256): A hi/lo planes from g_hidden ----
    {
        int r  = tid >> 2;              // 0..127
        int cg = tid & 3;               // 64-col group
        float2 h = reinterpret_cast<const float2*>(g_hidden)[B0 + r];
        char* rowh = smem + r * A_STRIDE;
        char* rowl = rowh + A_PLANE;
        #pragma unroll
        for (int i = 0; i < 32; i++) {
            int n = 64 * cg + 2 * i;
            float v0 = fmaxf(fmaf(h.x, __ldg(&w1[2 * n]),     fmaf(h.y, __ldg(&w1[2 * n + 1]), __ldg(&b1[n]))),     0.0f);
            float v1 = fmaxf(fmaf(h.x, __ldg(&w1[2 * n + 2]), fmaf(h.y, __ldg(&w1[2 * n + 3]), __ldg(&b1[n + 1]))), 0.0f);
            __nv_bfloat16 h0 = __float2bfloat16(v0);
            __nv_bfloat16 h1 = __float2bfloat16(v1);
            float l0 = v0 - __bfloat162float(h0);
            float l1 = v1 - __bfloat162float(h1);
            __nv_bfloat162 hp; hp.x = h0; hp.y = h1;
            *reinterpret_cast<uint32_t*>(rowh + n * 2) = *reinterpret_cast<uint32_t*>(&hp);
            *reinterpret_cast<uint32_t*>(rowl + n * 2) = pack_bf16x2(l0, l1);
        }
    }
    __syncthreads();

    // per-lane ldmatrix address components
    const uint32_t a_base = sb + (m0 + (lane & 15)) * A_STRIDE + ((lane >> 4) * 8) * 2;
    const uint32_t w_base = sb + W_OFF + (n0 + (lane & 15)) * W_ROW + (lane >> 4) * 16;

    // ---- 3 GEMM layers ----
    for (int L = 0; L < 3; L++) {
        float acc[2][8][4];
        #pragma unroll
        for (int t = 0; t < 2; t++)
            #pragma unroll
            for (int j = 0; j < 8; j++)
                #pragma unroll
                for (int q = 0; q < 4; q++) acc[t][j][q] = 0.0f;

        for (int kc = 0; kc < 8; kc++) {
            asm volatile("cp.async.wait_group 1;" ::: "memory");
            __syncthreads();
            const int buf = kc & 1;
            const uint32_t wbuf = w_base + buf * W_BUF;

            #pragma unroll
            for (int ks = 0; ks < 2; ks++) {
                const int kg = kc * 32 + ks * 16;     // global k for A
                const int kl = ks * 16;               // local k within W chunk
                uint32_t a_hi[2][4], a_lo[2][4];
                #pragma unroll
                for (int t = 0; t < 2; t++) {
                    LDSM4(a_hi[t], a_base + (t * 16) * A_STRIDE + kg * 2);
                    LDSM4(a_lo[t], a_base + A_PLANE + (t * 16) * A_STRIDE + kg * 2);
                }
                #pragma unroll
                for (int half = 0; half < 2; half++) {     // n sub-range of 32
                    uint32_t wh[8], wl[8];
                    LDSM4(wh,     wbuf + (half * 32)      * W_ROW + kl * 2);
                    LDSM4(wh + 4, wbuf + (half * 32 + 16) * W_ROW + kl * 2);
                    LDSM4(wl,     wbuf + W_PLANE + (half * 32)      * W_ROW + kl * 2);
                    LDSM4(wl + 4, wbuf + W_PLANE + (half * 32 + 16) * W_ROW + kl * 2);
                    #pragma unroll
                    for (int q = 0; q < 2; q++) {          // which x4 group (n16)
                        #pragma unroll
                        for (int s = 0; s < 2; s++) {      // n8 tile within group
                            int j = half * 4 + q * 2 + s;
                            uint32_t bh0 = wh[q * 4 + s], bh1 = wh[q * 4 + 2 + s];
                            uint32_t bl0 = wl[q * 4 + s], bl1 = wl[q * 4 + 2 + s];
                            #pragma unroll
                            for (int t = 0; t < 2; t++) {
                                MMA_BF16(acc[t][j], a_hi[t], bh0, bh1);
                                MMA_BF16(acc[t][j], a_lo[t], bh0, bh1);
                                MMA_BF16(acc[t][j], a_hi[t], bl0, bl1);
                            }
                        }
                    }
                }
            }
            __syncthreads();   // chunk consumed; safe to overwrite buffer
            int nk = kc + 2;
            if (nk < 8)            load_chunk(sb, buf, L, nk, tid);
            else if (L < 2)        load_chunk(sb, buf, L + 1, nk - 8, tid);
        }

        if (L < 2) {
            // epilogue: A_next = relu(D + bias) -> hi/lo planes (in place over A)
            const float* bias = (L == 0) ? b2 : b3;
            #pragma unroll
            for (int t = 0; t < 2; t++) {
                int r0 = m0 + 16 * t + (lane >> 2);
                char* ph0 = smem + r0 * A_STRIDE;
                char* ph1 = smem + (r0 + 8) * A_STRIDE;
                #pragma unroll
                for (int j = 0; j < 8; j++) {
                    int n = n0 + 8 * j + 2 * (lane & 3);
                    float bn0 = __ldg(&bias[n]), bn1 = __ldg(&bias[n + 1]);
                    float v0 = fmaxf(acc[t][j][0] + bn0, 0.0f);
                    float v1 = fmaxf(acc[t][j][1] + bn1, 0.0f);
                    float v2 = fmaxf(acc[t][j][2] + bn0, 0.0f);
                    float v3 = fmaxf(acc[t][j][3] + bn1, 0.0f);
                    __nv_bfloat16 q0 = __float2bfloat16(v0), q1 = __float2bfloat16(v1);
                    __nv_bfloat16 q2 = __float2bfloat16(v2), q3 = __float2bfloat16(v3);
                    __nv_bfloat162 p01; p01.x = q0; p01.y = q1;
                    __nv_bfloat162 p23; p23.x = q2; p23.y = q3;
                    *reinterpret_cast<uint32_t*>(ph0 + n * 2) = *reinterpret_cast<uint32_t*>(&p01);
                    *reinterpret_cast<uint32_t*>(ph1 + n * 2) = *reinterpret_cast<uint32_t*>(&p23);
                    *reinterpret_cast<uint32_t*>(ph0 + A_PLANE + n * 2) =
                        pack_bf16x2(v0 - __bfloat162float(q0), v1 - __bfloat162float(q1));
                    *reinterpret_cast<uint32_t*>(ph1 + A_PLANE + n * 2) =
                        pack_bf16x2(v2 - __bfloat162float(q2), v3 - __bfloat162float(q3));
                }
            }
            __syncthreads();
        } else {
            // final: v = relu(D + b4); out = v . w5^T + b5
            float* osum = reinterpret_cast<float*>(smem + OSUM_OFF);
            if (tid < 256) osum[tid] = 0.0f;
            __syncthreads();

            float s[2][2][2];
            #pragma unroll
            for (int t = 0; t < 2; t++)
                #pragma unroll
                for (int rh = 0; rh < 2; rh++)
                    s[t][rh][0] = s[t][rh][1] = 0.0f;

            #pragma unroll
            for (int t = 0; t < 2; t++) {
                #pragma unroll
                for (int j = 0; j < 8; j++) {
                    int n = n0 + 8 * j + 2 * (lane & 3);
                    float bn0 = __ldg(&b4[n]), bn1 = __ldg(&b4[n + 1]);
                    float w50 = __ldg(&w5[n]),       w51 = __ldg(&w5[n + 1]);
                    float w60 = __ldg(&w5[256 + n]), w61 = __ldg(&w5[256 + n + 1]);
                    float v0 = fmaxf(acc[t][j][0] + bn0, 0.0f);
                    float v1 = fmaxf(acc[t][j][1] + bn1, 0.0f);
                    float v2 = fmaxf(acc[t][j][2] + bn0, 0.0f);
                    float v3 = fmaxf(acc[t][j][3] + bn1, 0.0f);
                    s[t][0][0] = fmaf(v0, w50, fmaf(v1, w51, s[t][0][0]));
                    s[t][0][1] = fmaf(v0, w60, fmaf(v1, w61, s[t][0][1]));
                    s[t][1][0] = fmaf(v2, w50, fmaf(v3, w51, s[t][1][0]));
                    s[t][1][1] = fmaf(v2, w60, fmaf(v3, w61, s[t][1][1]));
                }
            }
            // quad reduce across lanes sharing the same rows (lane & 3)
            #pragma unroll
            for (int t = 0; t < 2; t++)
                #pragma unroll
                for (int rh = 0; rh < 2; rh++)
                    #pragma unroll
                    for (int c = 0; c < 2; c++) {
                        float v = s[t][rh][c];
                        v += __shfl_xor_sync(0xFFFFFFFF, v, 1);
                        v += __shfl_xor_sync(0xFFFFFFFF, v, 2);
                        s[t][rh][c] = v;
                    }
            if ((lane & 3) == 0) {
                #pragma unroll
                for (int t = 0; t < 2; t++) {
                    int r0 = m0 + 16 * t + (lane >> 2);
                    atomicAdd(&osum[2 * r0 + 0],       s[t][0][0]);
                    atomicAdd(&osum[2 * r0 + 1],       s[t][0][1]);
                    atomicAdd(&osum[2 * (r0 + 8) + 0], s[t][1][0]);
                    atomicAdd(&osum[2 * (r0 + 8) + 1], s[t][1][1]);
                }
            }
            __syncthreads();
            if (tid < 256) {
                int r = tid >> 1, c = tid & 1;
                out[(B0 + r) * 2 + c] = osum[tid] + __ldg(&b5[c]);
            }
        }
    }
}

// ======================= launch =======================
extern "C" void kernel_launch(void* const* d_in, const int* in_sizes, int n_in,
                              void* d_out, int out_size)
{
    const float* x    = (const float*)d_in[0];
    const float* w_ih = (const float*)d_in[1];
    const float* b_ih = (const float*)d_in[2];
    const float* w_hh = (const float*)d_in[3];
    const float* b_hh = (const float*)d_in[4];
    const float* w1   = (const float*)d_in[5];
    const float* b1   = (const float*)d_in[6];
    const float* w2   = (const float*)d_in[7];
    const float* b2   = (const float*)d_in[8];
    const float* w3   = (const float*)d_in[9];
    const float* b3   = (const float*)d_in[10];
    const float* w4   = (const float*)d_in[11];
    const float* b4   = (const float*)d_in[12];
    const float* w5   = (const float*)d_in[13];
    const float* b5   = (const float*)d_in[14];
    float* out        = (float*)d_out;

    prep_w_kernel<<<3 * 65536 / 256, 256>>>(w2, w3, w4);
    rnn_kernel<<<BATCH / 256, 256>>>(x, w_ih, b_ih, w_hh, b_hh);

    cudaFuncSetAttribute(mlp_mma_kernel, cudaFuncAttributeMaxDynamicSharedMemorySize, SMEM_TOTAL);
    mlp_mma_kernel<<<BATCH / MT, NTH, SMEM_TOTAL>>>(w1, b1, b2, b3, b4, w5, b5, out);
}

// round 10
// speedup vs baseline: 3.4790x; 1.2171x over previous
#include <cuda_runtime.h>
#include <cuda_fp16.h>
#include <cstdint>

#define SEQ    512
#define BATCH  65536

// ---------------- MLP config ----------------
#define MT        128               // batch rows per CTA
#define NTH       512               // threads (16 warps: 2 M-groups x 8 N-groups)
#define A_STRIDE  528               // bytes per A row (512 + 16 pad; 132 words, 132%32=4 -> conflict-free)
#define A_PLANE   (MT * A_STRIDE)   // 67584 B (single fp16 plane)
#define W_OFF     A_PLANE           // 67584
#define W_ROW     80                // bytes per W row (64 + 16 pad; 20 words, conflict-free)
#define W_PLANE   (256 * W_ROW)     // 20480 B (256 n-rows x 32 k fp16)
#define W_BUF     (2 * W_PLANE)     // hi+lo planes per k-chunk buffer = 40960
#define OSUM_OFF  (W_OFF + 2 * W_BUF)   // 149504
#define SMEM_TOTAL (OSUM_OFF + 1024)    // 150528

__device__ float g_hidden[BATCH * 2];
// weight images: [3 layers][2 planes (hi,lo)][8 k-chunks] x [256 n][32 k] fp16, 16KB each
__device__ __align__(1024) __half g_wimg[48 * 8192];

// ======================= helpers =======================
__device__ __forceinline__ uint32_t smem_u32(const void* p) {
    uint32_t a;
    asm("{ .reg .u64 t; cvta.to.shared.u64 t, %1; cvt.u32.u64 %0, t; }" : "=r"(a) : "l"(p));
    return a;
}

#define LDSM4(r, addr) \
    asm volatile("ldmatrix.sync.aligned.m8n8.x4.shared.b16 {%0,%1,%2,%3}, [%4];" \
                 : "=r"((r)[0]), "=r"((r)[1]), "=r"((r)[2]), "=r"((r)[3]) : "r"(addr))

#define MMA_F16(d, a, b0, b1) \
    asm volatile("mma.sync.aligned.m16n8k16.row.col.f32.f16.f16.f32 " \
                 "{%0,%1,%2,%3},{%4,%5,%6,%7},{%8,%9},{%0,%1,%2,%3};" \
                 : "+f"((d)[0]), "+f"((d)[1]), "+f"((d)[2]), "+f"((d)[3]) \
                 : "r"((a)[0]), "r"((a)[1]), "r"((a)[2]), "r"((a)[3]), "r"(b0), "r"(b1))

__device__ __forceinline__ uint32_t pack_h2(float a, float b) {
    __half2 t = __floats2half2_rn(a, b);
    return *reinterpret_cast<uint32_t*>(&t);
}

// ======================= RNN scan =======================
__device__ __forceinline__ float tanh_hw(float x) {
    float y; asm("tanh.approx.f32 %0, %1;" : "=f"(y) : "f"(x)); return y;
}

__global__ __launch_bounds__(64) void rnn_kernel(
    const float* __restrict__ x,
    const float* __restrict__ w_ih, const float* __restrict__ b_ih,
    const float* __restrict__ w_hh, const float* __restrict__ b_hh)
{
    int b = blockIdx.x * blockDim.x + threadIdx.x;
    float a00 = w_ih[0], a01 = w_ih[1], a10 = w_ih[2], a11 = w_ih[3];
    float u00 = w_hh[0], u01 = w_hh[1], u10 = w_hh[2], u11 = w_hh[3];
    float c0 = b_ih[0] + b_hh[0];
    float c1 = b_ih[1] + b_hh[1];

    float h0 = 0.0f, h1 = 0.0f;
    const float2* xp = reinterpret_cast<const float2*>(x) + b;

    #pragma unroll 8
    for (int t = 0; t < SEQ; t++) {
        float2 xv = xp[(size_t)t * BATCH];
        float p0 = fmaf(u01, h1, fmaf(u00, h0, fmaf(a01, xv.y, fmaf(a00, xv.x, c0))));
        float p1 = fmaf(u11, h1, fmaf(u10, h0, fmaf(a11, xv.y, fmaf(a10, xv.x, c1))));
        h0 = tanh_hw(p0);
        h1 = tanh_hw(p1);
    }
    reinterpret_cast<float2*>(g_hidden)[b] = make_float2(h0, h1);
}

// ======================= weight prep: fp32 -> fp16 hi/lo chunk images =======================
__global__ __launch_bounds__(256) void prep_w_kernel(
    const float* __restrict__ w2, const float* __restrict__ w3, const float* __restrict__ w4)
{
    int idx = blockIdx.x * blockDim.x + threadIdx.x;   // 0 .. 3*65536-1
    int L = idx >> 16;
    int r = idx & 65535;          // n*256 + k
    int n = r >> 8, k = r & 255;
    const float* W = (L == 0) ? w2 : (L == 1) ? w3 : w4;
    float v = W[r];
    __half h = __float2half_rn(v);
    __half l = __float2half_rn(v - __half2float(h));
    int kc = k >> 5, kk = k & 31;
    size_t base = ((size_t)((L * 2) * 8 + kc)) * 8192 + n * 32 + kk;
    g_wimg[base]            = h;   // hi plane image
    g_wimg[base + 8 * 8192] = l;   // lo plane image
}

// ======================= fused HMMA MLP =======================
__device__ __forceinline__ void load_chunk(uint32_t sb, int buf, int L, int kc, int tid) {
    #pragma unroll
    for (int i = 0; i < 4; i++) {
        int g  = tid + i * NTH;        // 0..2047 (2 planes x 1024 granules of 16B)
        int p  = g >> 10;
        int gg = g & 1023;
        int n  = gg >> 2, c = gg & 3;
        uint32_t dst = sb + W_OFF + buf * W_BUF + p * W_PLANE + n * W_ROW + c * 16;
        const void* src = (const char*)g_wimg +
            (((size_t)((L * 2 + p) * 8 + kc)) << 14) + ((size_t)gg << 4);
        asm volatile("cp.async.cg.shared.global [%0], [%1], 16;" :: "r"(dst), "l"(src));
    }
    asm volatile("cp.async.commit_group;" ::: "memory");
}

__global__ __launch_bounds__(NTH, 1) void mlp_mma_kernel(
    const float* __restrict__ w1, const float* __restrict__ b1,
    const float* __restrict__ b2, const float* __restrict__ b3,
    const float* __restrict__ b4,
    const float* __restrict__ w5, const float* __restrict__ b5,
    float* __restrict__ out)
{
    extern __shared__ char smem[];
    const uint32_t sb = smem_u32(smem);
    const int tid  = threadIdx.x;
    const int lane = tid & 31;
    const int wrp  = tid >> 5;
    const int wm   = wrp >> 3;          // M-group 0..1
    const int wn   = wrp & 7;           // N-group 0..7
    const int m0   = 64 * wm;
    const int n0   = 32 * wn;
    const int B0   = blockIdx.x * MT;

    // prefetch first two W k-chunks of layer 0
    load_chunk(sb, 0, 0, 0, tid);
    load_chunk(sb, 1, 0, 1, tid);

    // ---- layer 1 (2 -> 256): A fp16 plane from g_hidden ----
    {
        int r  = tid >> 2;              // 0..127
        int cg = tid & 3;               // 64-col group
        float2 h = reinterpret_cast<const float2*>(g_hidden)[B0 + r];
        char* row = smem + r * A_STRIDE;
        #pragma unroll
        for (int i = 0; i < 32; i++) {
            int n = 64 * cg + 2 * i;
            float v0 = fmaxf(fmaf(h.x, __ldg(&w1[2 * n]),     fmaf(h.y, __ldg(&w1[2 * n + 1]), __ldg(&b1[n]))),     0.0f);
            float v1 = fmaxf(fmaf(h.x, __ldg(&w1[2 * n + 2]), fmaf(h.y, __ldg(&w1[2 * n + 3]), __ldg(&b1[n + 1]))), 0.0f);
            *reinterpret_cast<uint32_t*>(row + n * 2) = pack_h2(v0, v1);
        }
    }
    __syncthreads();

    // per-lane ldmatrix address components
    const uint32_t a_base = sb + (m0 + (lane & 15)) * A_STRIDE + (lane >> 4) * 16;
    const uint32_t w_base = sb + W_OFF + (n0 + (lane & 15)) * W_ROW + (lane >> 4) * 16;

    // ---- 3 GEMM layers ----
    for (int L = 0; L < 3; L++) {
        float acc[4][4][4];
        #pragma unroll
        for (int t = 0; t < 4; t++)
            #pragma unroll
            for (int j = 0; j < 4; j++)
                #pragma unroll
                for (int q = 0; q < 4; q++) acc[t][j][q] = 0.0f;

        for (int kc = 0; kc < 8; kc++) {
            if (L == 2 && kc == 7)
                asm volatile("cp.async.wait_group 0;" ::: "memory");
            else
                asm volatile("cp.async.wait_group 1;" ::: "memory");
            __syncthreads();
            const int buf = kc & 1;
            const uint32_t wbuf = w_base + buf * W_BUF;

            #pragma unroll
            for (int ks = 0; ks < 2; ks++) {
                const int kg = kc * 32 + ks * 16;     // global k for A
                const int kl = ks * 16;               // local k within W chunk
                uint32_t a[4][4];
                #pragma unroll
                for (int t = 0; t < 4; t++)
                    LDSM4(a[t], a_base + (16 * t) * A_STRIDE + kg * 2);
                uint32_t wh[8], wl[8];
                LDSM4(wh,     wbuf +               kl * 2);
                LDSM4(wh + 4, wbuf + 16 * W_ROW  + kl * 2);
                LDSM4(wl,     wbuf + W_PLANE               + kl * 2);
                LDSM4(wl + 4, wbuf + W_PLANE + 16 * W_ROW  + kl * 2);
                #pragma unroll
                for (int j = 0; j < 4; j++) {         // n8 tiles within n32
                    int q = j >> 1, s = j & 1;
                    uint32_t bh0 = wh[q * 4 + s], bh1 = wh[q * 4 + 2 + s];
                    uint32_t bl0 = wl[q * 4 + s], bl1 = wl[q * 4 + 2 + s];
                    #pragma unroll
                    for (int t = 0; t < 4; t++) {
                        MMA_F16(acc[t][j], a[t], bh0, bh1);
                        MMA_F16(acc[t][j], a[t], bl0, bl1);
                    }
                }
            }
            __syncthreads();   // chunk consumed; safe to overwrite buffer
            int nk = kc + 2;
            if (nk < 8)            load_chunk(sb, buf, L, nk, tid);
            else if (L < 2)        load_chunk(sb, buf, L + 1, nk - 8, tid);
        }

        if (L < 2) {
            // epilogue: A_next = fp16(relu(D + bias))
            const float* bias = (L == 0) ? b2 : b3;
            #pragma unroll
            for (int t = 0; t < 4; t++) {
                int r0 = m0 + 16 * t + (lane >> 2);
                char* p0 = smem + r0 * A_STRIDE;
                char* p1 = smem + (r0 + 8) * A_STRIDE;
                #pragma unroll
                for (int j = 0; j < 4; j++) {
                    int n = n0 + 8 * j + 2 * (lane & 3);
                    float bn0 = __ldg(&bias[n]), bn1 = __ldg(&bias[n + 1]);
                    float v0 = fmaxf(acc[t][j][0] + bn0, 0.0f);
                    float v1 = fmaxf(acc[t][j][1] + bn1, 0.0f);
                    float v2 = fmaxf(acc[t][j][2] + bn0, 0.0f);
                    float v3 = fmaxf(acc[t][j][3] + bn1, 0.0f);
                    *reinterpret_cast<uint32_t*>(p0 + n * 2) = pack_h2(v0, v1);
                    *reinterpret_cast<uint32_t*>(p1 + n * 2) = pack_h2(v2, v3);
                }
            }
            __syncthreads();
        } else {
            // final: v = relu(D + b4); out = v . w5^T + b5
            float* osum = reinterpret_cast<float*>(smem + OSUM_OFF);
            if (tid < 256) osum[tid] = 0.0f;
            __syncthreads();

            float s[4][2][2];
            #pragma unroll
            for (int t = 0; t < 4; t++)
                #pragma unroll
                for (int rh = 0; rh < 2; rh++)
                    s[t][rh][0] = s[t][rh][1] = 0.0f;

            #pragma unroll
            for (int t = 0; t < 4; t++) {
                #pragma unroll
                for (int j = 0; j < 4; j++) {
                    int n = n0 + 8 * j + 2 * (lane & 3);
                    float bn0 = __ldg(&b4[n]), bn1 = __ldg(&b4[n + 1]);
                    float w50 = __ldg(&w5[n]),       w51 = __ldg(&w5[n + 1]);
                    float w60 = __ldg(&w5[256 + n]), w61 = __ldg(&w5[256 + n + 1]);
                    float v0 = fmaxf(acc[t][j][0] + bn0, 0.0f);
                    float v1 = fmaxf(acc[t][j][1] + bn1, 0.0f);
                    float v2 = fmaxf(acc[t][j][2] + bn0, 0.0f);
                    float v3 = fmaxf(acc[t][j][3] + bn1, 0.0f);
                    s[t][0][0] = fmaf(v0, w50, fmaf(v1, w51, s[t][0][0]));
                    s[t][0][1] = fmaf(v0, w60, fmaf(v1, w61, s[t][0][1]));
                    s[t][1][0] = fmaf(v2, w50, fmaf(v3, w51, s[t][1][0]));
                    s[t][1][1] = fmaf(v2, w60, fmaf(v3, w61, s[t][1][1]));
                }
            }
            // reduce across the 4 lanes sharing the same rows (lane&3 varies)
            #pragma unroll
            for (int t = 0; t < 4; t++)
                #pragma unroll
                for (int rh = 0; rh < 2; rh++)
                    #pragma unroll
                    for (int c = 0; c < 2; c++) {
                        float v = s[t][rh][c];
                        v += __shfl_xor_sync(0xFFFFFFFF, v, 1);
                        v += __shfl_xor_sync(0xFFFFFFFF, v, 2);
                        s[t][rh][c] = v;
                    }
            if ((lane & 3) == 0) {
                #pragma unroll
                for (int t = 0; t < 4; t++) {
                    int r0 = m0 + 16 * t + (lane >> 2);
                    atomicAdd(&osum[2 * r0 + 0],       s[t][0][0]);
                    atomicAdd(&osum[2 * r0 + 1],       s[t][0][1]);
                    atomicAdd(&osum[2 * (r0 + 8) + 0], s[t][1][0]);
                    atomicAdd(&osum[2 * (r0 + 8) + 1], s[t][1][1]);
                }
            }
            __syncthreads();
            if (tid < 256) {
                int r = tid >> 1, c = tid & 1;
                out[(B0 + r) * 2 + c] = osum[tid] + __ldg(&b5[c]);
            }
        }
    }
}

// ======================= launch =======================
extern "C" void kernel_launch(void* const* d_in, const int* in_sizes, int n_in,
                              void* d_out, int out_size)
{
    const float* x    = (const float*)d_in[0];
    const float* w_ih = (const float*)d_in[1];
    const float* b_ih = (const float*)d_in[2];
    const float* w_hh = (const float*)d_in[3];
    const float* b_hh = (const float*)d_in[4];
    const float* w1   = (const float*)d_in[5];
    const float* b1   = (const float*)d_in[6];
    const float* w2   = (const float*)d_in[7];
    const float* b2   = (const float*)d_in[8];
    const float* w3   = (const float*)d_in[9];
    const float* b3   = (const float*)d_in[10];
    const float* w4   = (const float*)d_in[11];
    const float* b4   = (const float*)d_in[12];
    const float* w5   = (const float*)d_in[13];
    const float* b5   = (const float*)d_in[14];
    float* out        = (float*)d_out;

    prep_w_kernel<<<3 * 65536 / 256, 256>>>(w2, w3, w4);
    rnn_kernel<<<BATCH / 64, 64>>>(x, w_ih, b_ih, w_hh, b_hh);

    cudaFuncSetAttribute(mlp_mma_kernel, cudaFuncAttributeMaxDynamicSharedMemorySize, SMEM_TOTAL);
    mlp_mma_kernel<<<BATCH / MT, NTH, SMEM_TOTAL>>>(w1, b1, b2, b3, b4, w5, b5, out);
}

// round 12
// speedup vs baseline: 5.3112x; 1.5266x over previous
#include <cuda_runtime.h>
#include <cuda_fp16.h>
#include <cstdint>

#define SEQ    512
#define BATCH  65536

// ---------------- MLP config ----------------
#define MT        64                // batch rows per CTA
#define NTH       256               // threads (8 warps: 1 M-group x 8 N-groups)
#define A_STRIDE  528               // bytes per A row (132 words; 8 rows span all 32 banks)
#define A_PLANE   (MT * A_STRIDE)   // 33792 B (single fp16 plane)
#define W_OFF     A_PLANE           // 33792
#define W_ROW     80                // bytes per W row (20 words, conflict-free)
#define W_PLANE   (256 * W_ROW)     // 20480 B (256 n-rows x 32 k fp16, single plane)
#define OSUM_OFF  (W_OFF + 2 * W_PLANE)  // 74752 (double-buffered W)
#define SMEM_TOTAL (OSUM_OFF + 1024)     // 75776 -> 2 CTAs/SM

__device__ float g_hidden[BATCH * 2];
// weight images: [3 layers][8 k-chunks] x [256 n][32 k] fp16, 16KB each (single plane)
__device__ __align__(1024) __half g_wimg[24 * 8192];

// ======================= helpers =======================
__device__ __forceinline__ uint32_t smem_u32(const void* p) {
    uint32_t a;
    asm("{ .reg .u64 t; cvta.to.shared.u64 t, %1; cvt.u32.u64 %0, t; }" : "=r"(a) : "l"(p));
    return a;
}

#define LDSM4(r, addr) \
    asm volatile("ldmatrix.sync.aligned.m8n8.x4.shared.b16 {%0,%1,%2,%3}, [%4];" \
                 : "=r"((r)[0]), "=r"((r)[1]), "=r"((r)[2]), "=r"((r)[3]) : "r"(addr))

#define MMA_F16(d, a, b0, b1) \
    asm volatile("mma.sync.aligned.m16n8k16.row.col.f32.f16.f16.f32 " \
                 "{%0,%1,%2,%3},{%4,%5,%6,%7},{%8,%9},{%0,%1,%2,%3};" \
                 : "+f"((d)[0]), "+f"((d)[1]), "+f"((d)[2]), "+f"((d)[3]) \
                 : "r"((a)[0]), "r"((a)[1]), "r"((a)[2]), "r"((a)[3]), "r"(b0), "r"(b1))

__device__ __forceinline__ uint32_t pack_h2(float a, float b) {
    __half2 t = __floats2half2_rn(a, b);
    return *reinterpret_cast<uint32_t*>(&t);
}

// ======================= RNN scan =======================
__device__ __forceinline__ float tanh_hw(float x) {
    float y; asm("tanh.approx.f32 %0, %1;" : "=f"(y) : "f"(x)); return y;
}

__global__ __launch_bounds__(64) void rnn_kernel(
    const float* __restrict__ x,
    const float* __restrict__ w_ih, const float* __restrict__ b_ih,
    const float* __restrict__ w_hh, const float* __restrict__ b_hh)
{
    int b = blockIdx.x * blockDim.x + threadIdx.x;
    float a00 = w_ih[0], a01 = w_ih[1], a10 = w_ih[2], a11 = w_ih[3];
    float u00 = w_hh[0], u01 = w_hh[1], u10 = w_hh[2], u11 = w_hh[3];
    float c0 = b_ih[0] + b_hh[0];
    float c1 = b_ih[1] + b_hh[1];

    float h0 = 0.0f, h1 = 0.0f;
    const float2* xp = reinterpret_cast<const float2*>(x) + b;

    #pragma unroll 8
    for (int t = 0; t < SEQ; t++) {
        float2 xv = xp[(size_t)t * BATCH];
        float p0 = fmaf(u01, h1, fmaf(u00, h0, fmaf(a01, xv.y, fmaf(a00, xv.x, c0))));
        float p1 = fmaf(u11, h1, fmaf(u10, h0, fmaf(a11, xv.y, fmaf(a10, xv.x, c1))));
        h0 = tanh_hw(p0);
        h1 = tanh_hw(p1);
    }
    reinterpret_cast<float2*>(g_hidden)[b] = make_float2(h0, h1);
}

// ======================= weight prep: fp32 -> fp16 chunk images =======================
__global__ __launch_bounds__(256) void prep_w_kernel(
    const float* __restrict__ w2, const float* __restrict__ w3, const float* __restrict__ w4)
{
    int idx = blockIdx.x * blockDim.x + threadIdx.x;   // 0 .. 3*65536-1
    int L = idx >> 16;
    int r = idx & 65535;          // n*256 + k
    int n = r >> 8, k = r & 255;
    const float* W = (L == 0) ? w2 : (L == 1) ? w3 : w4;
    int kc = k >> 5, kk = k & 31;
    g_wimg[((size_t)(L * 8 + kc)) * 8192 + n * 32 + kk] = __float2half_rn(W[r]);
}

// ======================= fused HMMA MLP =======================
__device__ __forceinline__ void load_chunk(uint32_t sb, int buf, int L, int kc, int tid) {
    #pragma unroll
    for (int i = 0; i < 4; i++) {
        int g  = tid + i * NTH;        // 0..1023 granules of 16B
        int n  = g >> 2, c = g & 3;
        uint32_t dst = sb + W_OFF + buf * W_PLANE + n * W_ROW + c * 16;
        const void* src = (const char*)g_wimg +
            (((size_t)(L * 8 + kc)) << 14) + ((size_t)g << 4);
        asm volatile("cp.async.cg.shared.global [%0], [%1], 16;" :: "r"(dst), "l"(src));
    }
    asm volatile("cp.async.commit_group;" ::: "memory");
}

__global__ __launch_bounds__(NTH, 2) void mlp_mma_kernel(
    const float* __restrict__ w1, const float* __restrict__ b1,
    const float* __restrict__ b2, const float* __restrict__ b3,
    const float* __restrict__ b4,
    const float* __restrict__ w5, const float* __restrict__ b5,
    float* __restrict__ out)
{
    extern __shared__ char smem[];
    const uint32_t sb = smem_u32(smem);
    const int tid  = threadIdx.x;
    const int lane = tid & 31;
    const int wn   = tid >> 5;          // N-group 0..7 (warp tile m64 x n32)
    const int n0   = 32 * wn;
    const int B0   = blockIdx.x * MT;

    // prefetch first two W k-chunks of layer 0
    load_chunk(sb, 0, 0, 0, tid);
    load_chunk(sb, 1, 0, 1, tid);

    // ---- layer 1 (2 -> 256): A fp16 plane from g_hidden ----
    {
        int r  = tid >> 2;              // 0..63
        int cg = tid & 3;               // 64-col group
        float2 h = reinterpret_cast<const float2*>(g_hidden)[B0 + r];
        char* row = smem + r * A_STRIDE;
        #pragma unroll
        for (int i = 0; i < 32; i++) {
            int n = 64 * cg + 2 * i;
            float v0 = fmaxf(fmaf(h.x, __ldg(&w1[2 * n]),     fmaf(h.y, __ldg(&w1[2 * n + 1]), __ldg(&b1[n]))),     0.0f);
            float v1 = fmaxf(fmaf(h.x, __ldg(&w1[2 * n + 2]), fmaf(h.y, __ldg(&w1[2 * n + 3]), __ldg(&b1[n + 1]))), 0.0f);
            *reinterpret_cast<uint32_t*>(row + n * 2) = pack_h2(v0, v1);
        }
    }
    __syncthreads();

    // per-lane ldmatrix address components
    const uint32_t a_base = sb + (lane & 15) * A_STRIDE + (lane >> 4) * 16;
    const uint32_t w_base = sb + W_OFF + (n0 + (lane & 15)) * W_ROW + (lane >> 4) * 16;

    // ---- 3 GEMM layers ----
    for (int L = 0; L < 3; L++) {
        float acc[4][4][4];
        #pragma unroll
        for (int t = 0; t < 4; t++)
            #pragma unroll
            for (int j = 0; j < 4; j++)
                #pragma unroll
                for (int q = 0; q < 4; q++) acc[t][j][q] = 0.0f;

        for (int kc = 0; kc < 8; kc++) {
            if (L == 2 && kc == 7)
                asm volatile("cp.async.wait_group 0;" ::: "memory");
            else
                asm volatile("cp.async.wait_group 1;" ::: "memory");
            __syncthreads();
            const int buf = kc & 1;
            const uint32_t wbuf = w_base + buf * W_PLANE;

            #pragma unroll
            for (int ks = 0; ks < 2; ks++) {
                const int kg = kc * 32 + ks * 16;     // global k for A
                const int kl = ks * 16;               // local k within W chunk
                uint32_t a[4][4];
                #pragma unroll
                for (int t = 0; t < 4; t++)
                    LDSM4(a[t], a_base + (16 * t) * A_STRIDE + kg * 2);
                uint32_t wh[8];
                LDSM4(wh,     wbuf +              kl * 2);
                LDSM4(wh + 4, wbuf + 16 * W_ROW + kl * 2);
                #pragma unroll
                for (int j = 0; j < 4; j++) {         // n8 tiles within n32
                    int q = j >> 1, s = j & 1;
                    uint32_t b0 = wh[q * 4 + s], b1r = wh[q * 4 + 2 + s];
                    #pragma unroll
                    for (int t = 0; t < 4; t++)
                        MMA_F16(acc[t][j], a[t], b0, b1r);
                }
            }
            __syncthreads();   // chunk consumed; safe to overwrite buffer
            int nk = kc + 2;
            if (nk < 8)            load_chunk(sb, buf, L, nk, tid);
            else if (L < 2)        load_chunk(sb, buf, L + 1, nk - 8, tid);
        }

        if (L < 2) {
            // epilogue: A_next = fp16(relu(D + bias))
            const float* bias = (L == 0) ? b2 : b3;
            #pragma unroll
            for (int t = 0; t < 4; t++) {
                int r0 = 16 * t + (lane >> 2);            // 0..63 with +8 twin
                char* p0 = smem + r0 * A_STRIDE;
                char* p1 = smem + (r0 + 8) * A_STRIDE;
                #pragma unroll
                for (int j = 0; j < 4; j++) {
                    int n = n0 + 8 * j + 2 * (lane & 3);
                    float bn0 = __ldg(&bias[n]), bn1 = __ldg(&bias[n + 1]);
                    float v0 = fmaxf(acc[t][j][0] + bn0, 0.0f);
                    float v1 = fmaxf(acc[t][j][1] + bn1, 0.0f);
                    float v2 = fmaxf(acc[t][j][2] + bn0, 0.0f);
                    float v3 = fmaxf(acc[t][j][3] + bn1, 0.0f);
                    *reinterpret_cast<uint32_t*>(p0 + n * 2) = pack_h2(v0, v1);
                    *reinterpret_cast<uint32_t*>(p1 + n * 2) = pack_h2(v2, v3);
                }
            }
            __syncthreads();
        } else {
            // final: v = relu(D + b4); out = v . w5^T + b5
            float* osum = reinterpret_cast<float*>(smem + OSUM_OFF);
            if (tid < MT * 2) osum[tid] = 0.0f;
            __syncthreads();

            float s[4][2][2];
            #pragma unroll
            for (int t = 0; t < 4; t++)
                #pragma unroll
                for (int rh = 0; rh < 2; rh++)
                    s[t][rh][0] = s[t][rh][1] = 0.0f;

            #pragma unroll
            for (int t = 0; t < 4; t++) {
                #pragma unroll
                for (int j = 0; j < 4; j++) {
                    int n = n0 + 8 * j + 2 * (lane & 3);
                    float bn0 = __ldg(&b4[n]), bn1 = __ldg(&b4[n + 1]);
                    float w50 = __ldg(&w5[n]),       w51 = __ldg(&w5[n + 1]);
                    float w60 = __ldg(&w5[256 + n]), w61 = __ldg(&w5[256 + n + 1]);
                    float v0 = fmaxf(acc[t][j][0] + bn0, 0.0f);
                    float v1 = fmaxf(acc[t][j][1] + bn1, 0.0f);
                    float v2 = fmaxf(acc[t][j][2] + bn0, 0.0f);
                    float v3 = fmaxf(acc[t][j][3] + bn1, 0.0f);
                    s[t][0][0] = fmaf(v0, w50, fmaf(v1, w51, s[t][0][0]));
                    s[t][0][1] = fmaf(v0, w60, fmaf(v1, w61, s[t][0][1]));
                    s[t][1][0] = fmaf(v2, w50, fmaf(v3, w51, s[t][1][0]));
                    s[t][1][1] = fmaf(v2, w60, fmaf(v3, w61, s[t][1][1]));
                }
            }
            // reduce across the 4 lanes sharing the same rows (lane&3 varies)
            #pragma unroll
            for (int t = 0; t < 4; t++)
                #pragma unroll
                for (int rh = 0; rh < 2; rh++)
                    #pragma unroll
                    for (int c = 0; c < 2; c++) {
                        float v = s[t][rh][c];
                        v += __shfl_xor_sync(0xFFFFFFFF, v, 1);
                        v += __shfl_xor_sync(0xFFFFFFFF, v, 2);
                        s[t][rh][c] = v;
                    }
            if ((lane & 3) == 0) {
                #pragma unroll
                for (int t = 0; t < 4; t++) {
                    int r0 = 16 * t + (lane >> 2);
                    atomicAdd(&osum[2 * r0 + 0],       s[t][0][0]);
                    atomicAdd(&osum[2 * r0 + 1],       s[t][0][1]);
                    atomicAdd(&osum[2 * (r0 + 8) + 0], s[t][1][0]);
                    atomicAdd(&osum[2 * (r0 + 8) + 1], s[t][1][1]);
                }
            }
            __syncthreads();
            if (tid < MT * 2) {
                int r = tid >> 1, c = tid & 1;
                out[(B0 + r) * 2 + c] = osum[tid] + __ldg(&b5[c]);
            }
        }
    }
}

// ======================= launch =======================
extern "C" void kernel_launch(void* const* d_in, const int* in_sizes, int n_in,
                              void* d_out, int out_size)
{
    const float* x    = (const float*)d_in[0];
    const float* w_ih = (const float*)d_in[1];
    const float* b_ih = (const float*)d_in[2];
    const float* w_hh = (const float*)d_in[3];
    const float* b_hh = (const float*)d_in[4];
    const float* w1   = (const float*)d_in[5];
    const float* b1   = (const float*)d_in[6];
    const float* w2   = (const float*)d_in[7];
    const float* b2   = (const float*)d_in[8];
    const float* w3   = (const float*)d_in[9];
    const float* b3   = (const float*)d_in[10];
    const float* w4   = (const float*)d_in[11];
    const float* b4   = (const float*)d_in[12];
    const float* w5   = (const float*)d_in[13];
    const float* b5   = (const float*)d_in[14];
    float* out        = (float*)d_out;

    prep_w_kernel<<<3 * 65536 / 256, 256>>>(w2, w3, w4);
    rnn_kernel<<<BATCH / 64, 64>>>(x, w_ih, b_ih, w_hh, b_hh);

    cudaFuncSetAttribute(mlp_mma_kernel, cudaFuncAttributeMaxDynamicSharedMemorySize, SMEM_TOTAL);
    mlp_mma_kernel<<<BATCH / MT, NTH, SMEM_TOTAL>>>(w1, b1, b2, b3, b4, w5, b5, out);
}

// round 17
// speedup vs baseline: 5.4162x; 1.0198x over previous
#include <cuda_runtime.h>
#include <cuda_fp16.h>
#include <cstdint>

#define SEQ    512
#define BATCH  65536

// ---------------- MLP config ----------------
#define MT        64                // batch rows per CTA
#define NTH       128               // threads (4 warps: warp tile m64 x n64)
#define A_STRIDE  528               // bytes per A row (132 words; 8 rows span all 32 banks)
#define A_PLANE   (MT * A_STRIDE)   // 33792 B (single fp16 plane)
#define W_OFF     A_PLANE           // 33792
#define W_ROW     80                // bytes per W row (20 words, conflict-free)
#define W_PLANE   (256 * W_ROW)     // 20480 B (256 n-rows x 32 k fp16, single plane)
#define OSUM_OFF  (W_OFF + 2 * W_PLANE)  // 74752 (double-buffered W)
#define SMEM_TOTAL (OSUM_OFF + 1024)     // 75776 -> 2 CTAs/SM

__device__ float g_hidden[BATCH * 2];
// weight images: [3 layers][8 k-chunks] x [256 n][32 k] fp16, 16KB each (single plane)
__device__ __align__(1024) __half g_wimg[24 * 8192];

// ======================= helpers =======================
__device__ __forceinline__ uint32_t smem_u32(const void* p) {
    uint32_t a;
    asm("{ .reg .u64 t; cvta.to.shared.u64 t, %1; cvt.u32.u64 %0, t; }" : "=r"(a) : "l"(p));
    return a;
}

#define LDSM4(r, addr) \
    asm volatile("ldmatrix.sync.aligned.m8n8.x4.shared.b16 {%0,%1,%2,%3}, [%4];" \
                 : "=r"((r)[0]), "=r"((r)[1]), "=r"((r)[2]), "=r"((r)[3]) : "r"(addr))

#define MMA_F16(d, a, b0, b1) \
    asm volatile("mma.sync.aligned.m16n8k16.row.col.f32.f16.f16.f32 " \
                 "{%0,%1,%2,%3},{%4,%5,%6,%7},{%8,%9},{%0,%1,%2,%3};" \
                 : "+f"((d)[0]), "+f"((d)[1]), "+f"((d)[2]), "+f"((d)[3]) \
                 : "r"((a)[0]), "r"((a)[1]), "r"((a)[2]), "r"((a)[3]), "r"(b0), "r"(b1))

__device__ __forceinline__ uint32_t pack_h2(float a, float b) {
    __half2 t = __floats2half2_rn(a, b);
    return *reinterpret_cast<uint32_t*>(&t);
}

// ======================= RNN scan =======================
__device__ __forceinline__ float tanh_hw(float x) {
    float y; asm("tanh.approx.f32 %0, %1;" : "=f"(y) : "f"(x)); return y;
}

__global__ __launch_bounds__(64) void rnn_kernel(
    const float* __restrict__ x,
    const float* __restrict__ w_ih, const float* __restrict__ b_ih,
    const float* __restrict__ w_hh, const float* __restrict__ b_hh)
{
    int b = blockIdx.x * blockDim.x + threadIdx.x;
    float a00 = w_ih[0], a01 = w_ih[1], a10 = w_ih[2], a11 = w_ih[3];
    float u00 = w_hh[0], u01 = w_hh[1], u10 = w_hh[2], u11 = w_hh[3];
    float c0 = b_ih[0] + b_hh[0];
    float c1 = b_ih[1] + b_hh[1];

    float h0 = 0.0f, h1 = 0.0f;
    const float2* xp = reinterpret_cast<const float2*>(x) + b;

    #pragma unroll 8
    for (int t = 0; t < SEQ; t++) {
        float2 xv = xp[(size_t)t * BATCH];
        float p0 = fmaf(u01, h1, fmaf(u00, h0, fmaf(a01, xv.y, fmaf(a00, xv.x, c0))));
        float p1 = fmaf(u11, h1, fmaf(u10, h0, fmaf(a11, xv.y, fmaf(a10, xv.x, c1))));
        h0 = tanh_hw(p0);
        h1 = tanh_hw(p1);
    }
    reinterpret_cast<float2*>(g_hidden)[b] = make_float2(h0, h1);
}

// ======================= weight prep: fp32 -> fp16 chunk images =======================
__global__ __launch_bounds__(256) void prep_w_kernel(
    const float* __restrict__ w2, const float* __restrict__ w3, const float* __restrict__ w4)
{
    int idx = blockIdx.x * blockDim.x + threadIdx.x;   // 0 .. 3*65536-1
    int L = idx >> 16;
    int r = idx & 65535;          // n*256 + k
    int n = r >> 8, k = r & 255;
    const float* W = (L == 0) ? w2 : (L == 1) ? w3 : w4;
    int kc = k >> 5, kk = k & 31;
    g_wimg[((size_t)(L * 8 + kc)) * 8192 + n * 32 + kk] = __float2half_rn(W[r]);
}

// ======================= fused HMMA MLP =======================
__device__ __forceinline__ void load_chunk(uint32_t sb, int buf, int L, int kc, int tid) {
    #pragma unroll
    for (int i = 0; i < 8; i++) {
        int g  = tid + i * NTH;        // 0..1023 granules of 16B
        int n  = g >> 2, c = g & 3;
        uint32_t dst = sb + W_OFF + buf * W_PLANE + n * W_ROW + c * 16;
        const void* src = (const char*)g_wimg +
            (((size_t)(L * 8 + kc)) << 14) + ((size_t)g << 4);
        asm volatile("cp.async.cg.shared.global [%0], [%1], 16;" :: "r"(dst), "l"(src));
    }
    asm volatile("cp.async.commit_group;" ::: "memory");
}

__global__ __launch_bounds__(NTH, 2) void mlp_mma_kernel(
    const float* __restrict__ w1, const float* __restrict__ b1,
    const float* __restrict__ b2, const float* __restrict__ b3,
    const float* __restrict__ b4,
    const float* __restrict__ w5, const float* __restrict__ b5,
    float* __restrict__ out)
{
    extern __shared__ char smem[];
    const uint32_t sb = smem_u32(smem);
    const int tid  = threadIdx.x;
    const int lane = tid & 31;
    const int wn   = tid >> 5;          // N-group 0..3 (warp tile m64 x n64)
    const int n0   = 64 * wn;
    const int B0   = blockIdx.x * MT;

    // prefetch first two W k-chunks of layer 0
    load_chunk(sb, 0, 0, 0, tid);
    load_chunk(sb, 1, 0, 1, tid);

    // ---- layer 1 (2 -> 256): A fp16 plane from g_hidden ----
    {
        int r  = tid >> 1;              // 0..63
        int cg = tid & 1;               // 128-col group
        float2 h = reinterpret_cast<const float2*>(g_hidden)[B0 + r];
        char* row = smem + r * A_STRIDE;
        #pragma unroll
        for (int i = 0; i < 64; i++) {
            int n = 128 * cg + 2 * i;
            float v0 = fmaxf(fmaf(h.x, __ldg(&w1[2 * n]),     fmaf(h.y, __ldg(&w1[2 * n + 1]), __ldg(&b1[n]))),     0.0f);
            float v1 = fmaxf(fmaf(h.x, __ldg(&w1[2 * n + 2]), fmaf(h.y, __ldg(&w1[2 * n + 3]), __ldg(&b1[n + 1]))), 0.0f);
            *reinterpret_cast<uint32_t*>(row + n * 2) = pack_h2(v0, v1);
        }
    }
    __syncthreads();

    // per-lane ldmatrix address components
    const uint32_t a_base = sb + (lane & 15) * A_STRIDE + (lane >> 4) * 16;
    const uint32_t w_base = sb + W_OFF + (n0 + (lane & 15)) * W_ROW + (lane >> 4) * 16;

    // ---- 3 GEMM layers ----
    for (int L = 0; L < 3; L++) {
        float acc[4][8][4];
        #pragma unroll
        for (int t = 0; t < 4; t++)
            #pragma unroll
            for (int j = 0; j < 8; j++)
                #pragma unroll
                for (int q = 0; q < 4; q++) acc[t][j][q] = 0.0f;

        for (int kc = 0; kc < 8; kc++) {
            if (L == 2 && kc == 7)
                asm volatile("cp.async.wait_group 0;" ::: "memory");
            else
                asm volatile("cp.async.wait_group 1;" ::: "memory");
            __syncthreads();
            const int buf = kc & 1;
            const uint32_t wbuf = w_base + buf * W_PLANE;

            #pragma unroll
            for (int ks = 0; ks < 2; ks++) {
                const int kg = kc * 32 + ks * 16;     // global k for A
                const int kl = ks * 16;               // local k within W chunk
                uint32_t a[4][4];
                #pragma unroll
                for (int t = 0; t < 4; t++)
                    LDSM4(a[t], a_base + (16 * t) * A_STRIDE + kg * 2);
                uint32_t wh[16];
                LDSM4(wh,      wbuf +              kl * 2);
                LDSM4(wh + 4,  wbuf + 16 * W_ROW + kl * 2);
                LDSM4(wh + 8,  wbuf + 32 * W_ROW + kl * 2);
                LDSM4(wh + 12, wbuf + 48 * W_ROW + kl * 2);
                #pragma unroll
                for (int j = 0; j < 8; j++) {         // n8 tiles within n64
                    int g = j >> 1, s = j & 1;
                    uint32_t b0 = wh[g * 4 + s], b1r = wh[g * 4 + 2 + s];
                    #pragma unroll
                    for (int t = 0; t < 4; t++)
                        MMA_F16(acc[t][j], a[t], b0, b1r);
                }
            }
            __syncthreads();   // chunk consumed; safe to overwrite buffer
            int nk = kc + 2;
            if (nk < 8)            load_chunk(sb, buf, L, nk, tid);
            else if (L < 2)        load_chunk(sb, buf, L + 1, nk - 8, tid);
        }

        if (L < 2) {
            // epilogue: A_next = fp16(relu(D + bias))
            const float* bias = (L == 0) ? b2 : b3;
            #pragma unroll
            for (int t = 0; t < 4; t++) {
                int r0 = 16 * t + (lane >> 2);            // 0..63 with +8 twin
                char* p0 = smem + r0 * A_STRIDE;
                char* p1 = smem + (r0 + 8) * A_STRIDE;
                #pragma unroll
                for (int j = 0; j < 8; j++) {
                    int n = n0 + 8 * j + 2 * (lane & 3);
                    float bn0 = __ldg(&bias[n]), bn1 = __ldg(&bias[n + 1]);
                    float v0 = fmaxf(acc[t][j][0] + bn0, 0.0f);
                    float v1 = fmaxf(acc[t][j][1] + bn1, 0.0f);
                    float v2 = fmaxf(acc[t][j][2] + bn0, 0.0f);
                    float v3 = fmaxf(acc[t][j][3] + bn1, 0.0f);
                    *reinterpret_cast<uint32_t*>(p0 + n * 2) = pack_h2(v0, v1);
                    *reinterpret_cast<uint32_t*>(p1 + n * 2) = pack_h2(v2, v3);
                }
            }
            __syncthreads();
        } else {
            // final: v = relu(D + b4); out = v . w5^T + b5
            float* osum = reinterpret_cast<float*>(smem + OSUM_OFF);
            osum[tid] = 0.0f;      // NTH == MT*2 == 128
            __syncthreads();

            float s[4][2][2];
            #pragma unroll
            for (int t = 0; t < 4; t++)
                #pragma unroll
                for (int rh = 0; rh < 2; rh++)
                    s[t][rh][0] = s[t][rh][1] = 0.0f;

            #pragma unroll
            for (int t = 0; t < 4; t++) {
                #pragma unroll
                for (int j = 0; j < 8; j++) {
                    int n = n0 + 8 * j + 2 * (lane & 3);
                    float bn0 = __ldg(&b4[n]), bn1 = __ldg(&b4[n + 1]);
                    float w50 = __ldg(&w5[n]),       w51 = __ldg(&w5[n + 1]);
                    float w60 = __ldg(&w5[256 + n]), w61 = __ldg(&w5[256 + n + 1]);
                    float v0 = fmaxf(acc[t][j][0] + bn0, 0.0f);
                    float v1 = fmaxf(acc[t][j][1] + bn1, 0.0f);
                    float v2 = fmaxf(acc[t][j][2] + bn0, 0.0f);
                    float v3 = fmaxf(acc[t][j][3] + bn1, 0.0f);
                    s[t][0][0] = fmaf(v0, w50, fmaf(v1, w51, s[t][0][0]));
                    s[t][0][1] = fmaf(v0, w60, fmaf(v1, w61, s[t][0][1]));
                    s[t][1][0] = fmaf(v2, w50, fmaf(v3, w51, s[t][1][0]));
                    s[t][1][1] = fmaf(v2, w60, fmaf(v3, w61, s[t][1][1]));
                }
            }
            // reduce across the 4 lanes sharing the same rows (lane&3 varies)
            #pragma unroll
            for (int t = 0; t < 4; t++)
                #pragma unroll
                for (int rh = 0; rh < 2; rh++)
                    #pragma unroll
                    for (int c = 0; c < 2; c++) {
                        float v = s[t][rh][c];
                        v += __shfl_xor_sync(0xFFFFFFFF, v, 1);
                        v += __shfl_xor_sync(0xFFFFFFFF, v, 2);
                        s[t][rh][c] = v;
                    }
            if ((lane & 3) == 0) {
                #pragma unroll
                for (int t = 0; t < 4; t++) {
                    int r0 = 16 * t + (lane >> 2);
                    atomicAdd(&osum[2 * r0 + 0],       s[t][0][0]);
                    atomicAdd(&osum[2 * r0 + 1],       s[t][0][1]);
                    atomicAdd(&osum[2 * (r0 + 8) + 0], s[t][1][0]);
                    atomicAdd(&osum[2 * (r0 + 8) + 1], s[t][1][1]);
                }
            }
            __syncthreads();
            {
                int r = tid >> 1, c = tid & 1;
                out[(B0 + r) * 2 + c] = osum[tid] + __ldg(&b5[c]);
            }
        }
    }
}

// ======================= launch =======================
extern "C" void kernel_launch(void* const* d_in, const int* in_sizes, int n_in,
                              void* d_out, int out_size)
{
    const float* x    = (const float*)d_in[0];
    const float* w_ih = (const float*)d_in[1];
    const float* b_ih = (const float*)d_in[2];
    const float* w_hh = (const float*)d_in[3];
    const float* b_hh = (const float*)d_in[4];
    const float* w1   = (const float*)d_in[5];
    const float* b1   = (const float*)d_in[6];
    const float* w2   = (const float*)d_in[7];
    const float* b2   = (const float*)d_in[8];
    const float* w3   = (const float*)d_in[9];
    const float* b3   = (const float*)d_in[10];
    const float* w4   = (const float*)d_in[11];
    const float* b4   = (const float*)d_in[12];
    const float* w5   = (const float*)d_in[13];
    const float* b5   = (const float*)d_in[14];
    float* out        = (float*)d_out;

    prep_w_kernel<<<3 * 65536 / 256, 256>>>(w2, w3, w4);
    rnn_kernel<<<BATCH / 64, 64>>>(x, w_ih, b_ih, w_hh, b_hh);

    cudaFuncSetAttribute(mlp_mma_kernel, cudaFuncAttributeMaxDynamicSharedMemorySize, SMEM_TOTAL);
    mlp_mma_kernel<<<BATCH / MT, NTH, SMEM_TOTAL>>>(w1, b1, b2, b3, b4, w5, b5, out);
}